// round 13
// baseline (speedup 1.0000x reference)
#include <cuda_runtime.h>
#include <cuda_bf16.h>
#include <cuda_fp16.h>
#include <cuda_fp8.h>
#include <math.h>
#include <stdint.h>

// Problem constants (fixed by the dataset)
#define BATCH 8
#define NPTS  2048
#define DIM   512
#define KN    3
#define NROWS (BATCH * NPTS)   // 16384
#define FCK   1024             // 2-term fp16 split fc: 2 * DIM
#define NTILE 16               // 2048 / 128
#define NTRI  136              // NTILE*(NTILE+1)/2 upper-triangle tiles

// ---------------- scratch (static device memory; no allocs allowed) ----------
__device__ uint8_t       g_xq [(size_t)NROWS * DIM];            // 8 MB e4m3 normalized
__device__ float         g_inorm[(size_t)NROWS];                // 64 KB inverse norms
__device__ __nv_bfloat16 g_disb[(size_t)BATCH * NPTS * NPTS];   // 67 MB bf16 scores
__device__ int           g_idx8[(size_t)NROWS * 8];
__device__ int           g_idx [(size_t)NROWS * KN];
__device__ __half        g_fcA[(size_t)NROWS * FCK];            // 32 MB [hi, lo] fp16
__device__ __half        g_fcB[(size_t)DIM * FCK];              // 1 MB  [hi, hi] fp16

// ============================ PTX helpers ======================================
__device__ __forceinline__ uint32_t smem_u32(const void* p) {
    uint32_t a;
    asm("{ .reg .u64 t; cvta.to.shared.u64 t, %1; cvt.u32.u64 %0, t; }"
        : "=r"(a) : "l"(p));
    return a;
}

#define CP_ASYNC16(saddr, gptr) \
    asm volatile("cp.async.cg.shared.global [%0], [%1], 16;" \
                 :: "r"(saddr), "l"(gptr) : "memory")
#define CP_COMMIT()  asm volatile("cp.async.commit_group;" ::: "memory")
#define CP_WAIT1()   asm volatile("cp.async.wait_group 1;" ::: "memory")
#define CP_WAIT0()   asm volatile("cp.async.wait_group 0;" ::: "memory")

#define LDMATRIX_X4(r, addr) \
    asm volatile("ldmatrix.sync.aligned.m8n8.x4.shared.b16 {%0,%1,%2,%3}, [%4];" \
        : "=r"((r)[0]), "=r"((r)[1]), "=r"((r)[2]), "=r"((r)[3]) : "r"(addr))

#define MMA_FP16(c, a, b0, b1) \
    asm volatile("mma.sync.aligned.m16n8k16.row.col.f32.f16.f16.f32 " \
        "{%0,%1,%2,%3}, {%4,%5,%6,%7}, {%8,%9}, {%0,%1,%2,%3};" \
        : "+f"((c)[0]), "+f"((c)[1]), "+f"((c)[2]), "+f"((c)[3]) \
        : "r"((a)[0]), "r"((a)[1]), "r"((a)[2]), "r"((a)[3]), "r"(b0), "r"(b1))

#define MMA_FP8(c, a, b0, b1) \
    asm volatile("mma.sync.aligned.m16n8k32.row.col.f32.e4m3.e4m3.f32 " \
        "{%0,%1,%2,%3}, {%4,%5,%6,%7}, {%8,%9}, {%0,%1,%2,%3};" \
        : "+f"((c)[0]), "+f"((c)[1]), "+f"((c)[2]), "+f"((c)[3]) \
        : "r"((a)[0]), "r"((a)[1]), "r"((a)[2]), "r"((a)[3]), "r"(b0), "r"(b1))

// GEMM mainloop on BYTE pointers: 3-stage cp.async pipeline, one barrier per
// chunk. Chunk = 128 rows x 128 bytes (SW128 swizzled). The byte layout is
// identical for fp16 (64 elems/row-chunk) and fp8 (128 elems/row-chunk);
// ldmatrix.b16 fragments byte-match both mma flavors.
#define GEMM_MAINLOOP_B(Ar, Br, ROWB, NK, MMAOP)                               \
    const int seg = tid & 7;                                                   \
    const int r0  = tid >> 3;                                                  \
    auto load_chunk = [&](int c, int stage) {                                  \
        const uint32_t dA = sbase + stage * 32768;                             \
        const uint32_t dB = dA + 16384;                                        \
        const size_t koff = (size_t)c * 128 + seg * 16;                        \
        _Pragma("unroll")                                                      \
        for (int it = 0; it < 4; ++it) {                                       \
            const int r = r0 + it * 32;                                        \
            uint32_t off = r * 128 + seg * 16;                                 \
            off ^= (off >> 3) & 0x70;                                          \
            CP_ASYNC16(dA + off, (Ar) + (size_t)r * (ROWB) + koff);            \
            CP_ASYNC16(dB + off, (Br) + (size_t)r * (ROWB) + koff);            \
        }                                                                      \
    };                                                                         \
    _Pragma("unroll")                                                          \
    for (int mt = 0; mt < 4; ++mt)                                             \
        _Pragma("unroll")                                                      \
        for (int nt = 0; nt < 4; ++nt)                                         \
            _Pragma("unroll")                                                  \
            for (int q = 0; q < 4; ++q) acc[mt][nt][q] = 0.0f;                 \
    const int nk = (NK);                                                       \
    load_chunk(0, 0);                                                          \
    CP_COMMIT();                                                               \
    load_chunk(1, 1);                                                          \
    CP_COMMIT();                                                               \
    const int mi = lane >> 3;                                                  \
    const int l7 = lane & 7;                                                   \
    _Pragma("unroll 1")                                                        \
    for (int c = 0; c < nk; ++c) {                                             \
        const int st = c % 3;                                                  \
        if (c + 1 < nk) { CP_WAIT1(); } else { CP_WAIT0(); }                   \
        __syncthreads();                                                       \
        if (c + 2 < nk) { load_chunk(c + 2, (c + 2) % 3); CP_COMMIT(); }       \
        const uint32_t tA = sbase + st * 32768;                                \
        const uint32_t tB = tA + 16384;                                        \
        _Pragma("unroll")                                                      \
        for (int ks = 0; ks < 4; ++ks) {                                       \
            uint32_t a[4][4], b[2][4];                                         \
            _Pragma("unroll")                                                  \
            for (int mt = 0; mt < 4; ++mt) {                                   \
                const int row = wr * 64 + mt * 16 + l7 + ((mi & 1) << 3);      \
                const int sg  = ks * 2 + (mi >> 1);                            \
                uint32_t off = row * 128 + sg * 16;                            \
                off ^= (off >> 3) & 0x70;                                      \
                LDMATRIX_X4(a[mt], tA + off);                                  \
            }                                                                  \
            _Pragma("unroll")                                                  \
            for (int np = 0; np < 2; ++np) {                                   \
                const int n  = wc * 32 + np * 16 + l7 + ((mi >> 1) << 3);      \
                const int sg = ks * 2 + (mi & 1);                              \
                uint32_t off = n * 128 + sg * 16;                              \
                off ^= (off >> 3) & 0x70;                                      \
                LDMATRIX_X4(b[np], tB + off);                                  \
            }                                                                  \
            _Pragma("unroll")                                                  \
            for (int mt = 0; mt < 4; ++mt)                                     \
                _Pragma("unroll")                                              \
                for (int nt = 0; nt < 4; ++nt)                                 \
                    MMAOP(acc[mt][nt], a[mt],                                  \
                          b[nt >> 1][(nt & 1) * 2], b[nt >> 1][(nt & 1) * 2 + 1]); \
        }                                                                      \
    }

// ---------------- 1. row L2-normalize: e4m3 copy + inverse norm ----------------
__global__ void __launch_bounds__(128) normalize_k(const float* __restrict__ feats)
{
    const size_t row = blockIdx.x;
    const float4 v = ((const float4*)(feats + row * DIM))[threadIdx.x];
    float ss = v.x * v.x + v.y * v.y + v.z * v.z + v.w * v.w;
    #pragma unroll
    for (int o = 16; o; o >>= 1) ss += __shfl_xor_sync(0xffffffffu, ss, o);
    __shared__ float s[4];
    if ((threadIdx.x & 31) == 0) s[threadIdx.x >> 5] = ss;
    __syncthreads();
    const float tot = s[0] + s[1] + s[2] + s[3];
    const float inv = 1.0f / fmaxf(sqrtf(tot), 1e-12f);
    const uint32_t q0 = (uint32_t)__nv_cvt_float_to_fp8(v.x * inv, __NV_SATFINITE, __NV_E4M3);
    const uint32_t q1 = (uint32_t)__nv_cvt_float_to_fp8(v.y * inv, __NV_SATFINITE, __NV_E4M3);
    const uint32_t q2 = (uint32_t)__nv_cvt_float_to_fp8(v.z * inv, __NV_SATFINITE, __NV_E4M3);
    const uint32_t q3 = (uint32_t)__nv_cvt_float_to_fp8(v.w * inv, __NV_SATFINITE, __NV_E4M3);
    ((uint32_t*)(g_xq + row * DIM))[threadIdx.x] = q0 | (q1 << 8) | (q2 << 16) | (q3 << 24);
    if (threadIdx.x == 0) g_inorm[row] = inv;
}

// ---------------- 2. symmetric similarity GEMM, fp8 inputs ---------------------
__global__ void __launch_bounds__(256, 2) gemm_sym_k(
    const uint8_t* __restrict__ xq, __nv_bfloat16* __restrict__ dis)
{
    extern __shared__ char smem_raw[];
    char* tiles = (char*)(((uintptr_t)smem_raw + 1023) & ~(uintptr_t)1023);
    const uint32_t sbase = smem_u32(tiles);

    int t = blockIdx.x, ti = 0;
    while (t >= NTILE - ti) { t -= NTILE - ti; ++ti; }
    const int tj = ti + t;
    const int brow = ti * 128, bcol = tj * 128;

    const uint8_t* base = xq + (size_t)blockIdx.z * NPTS * DIM;
    __nv_bfloat16* C = dis + (size_t)blockIdx.z * NPTS * NPTS;

    const int tid  = threadIdx.x;
    const int lane = tid & 31, wid = tid >> 5;
    const int wr = wid >> 2, wc = wid & 3;

    const uint8_t* Ar = base + (size_t)brow * DIM;
    const uint8_t* Br = base + (size_t)bcol * DIM;

    float acc[4][4][4];
    GEMM_MAINLOOP_B(Ar, Br, DIM, DIM / 128, MMA_FP8)

    // direct bf16 store (col even -> 4B-aligned bf162)
    const int rbase = wr * 64 + (lane >> 2);
    const int cbase = wc * 32 + (lane & 3) * 2;
    #pragma unroll
    for (int mt = 0; mt < 4; ++mt) {
        #pragma unroll
        for (int nt = 0; nt < 4; ++nt) {
            const int row = rbase + mt * 16;
            const int col = cbase + nt * 8;
            __nv_bfloat162 b0, b1;
            b0.x = __float2bfloat16(acc[mt][nt][0]);
            b0.y = __float2bfloat16(acc[mt][nt][1]);
            b1.x = __float2bfloat16(acc[mt][nt][2]);
            b1.y = __float2bfloat16(acc[mt][nt][3]);
            *(__nv_bfloat162*)(C + (size_t)(brow + row) * NPTS + bcol + col)     = b0;
            *(__nv_bfloat162*)(C + (size_t)(brow + row + 8) * NPTS + bcol + col) = b1;
        }
    }

    if (ti != tj) {
        __syncthreads();   // last chunk's ldmatrix reads must finish before reuse
        float* Cs = (float*)tiles;
        #pragma unroll
        for (int mt = 0; mt < 4; ++mt) {
            #pragma unroll
            for (int nt = 0; nt < 4; ++nt) {
                const int row = rbase + mt * 16;
                const int col = cbase + nt * 8;
                Cs[row * 129 + col]           = acc[mt][nt][0];
                Cs[row * 129 + col + 1]       = acc[mt][nt][1];
                Cs[(row + 8) * 129 + col]     = acc[mt][nt][2];
                Cs[(row + 8) * 129 + col + 1] = acc[mt][nt][3];
            }
        }
        __syncthreads();
        #pragma unroll 8
        for (int it2 = 0; it2 < 64; ++it2) {
            const int linear = it2 * 256 + tid;
            const int r2 = linear >> 7;
            const int c2 = linear & 127;
            C[(size_t)(bcol + r2) * NPTS + brow + c2] =
                __float2bfloat16(Cs[c2 * 129 + r2]);
        }
    }
}

// ---------------- 2b. fc GEMM: fp16 2-term split, relu store -------------------
__global__ void __launch_bounds__(256, 2) gemm_fc_k(
    const __half* __restrict__ A, const __half* __restrict__ B,
    float* __restrict__ C)
{
    extern __shared__ char smem_raw[];
    char* tiles = (char*)(((uintptr_t)smem_raw + 1023) & ~(uintptr_t)1023);
    const uint32_t sbase = smem_u32(tiles);

    const int tid  = threadIdx.x;
    const int lane = tid & 31, wid = tid >> 5;
    const int wr = wid >> 2, wc = wid & 3;
    const int brow = blockIdx.y * 128, bcol = blockIdx.x * 128;

    const uint8_t* Ar = (const uint8_t*)(A + (size_t)brow * FCK);
    const uint8_t* Br = (const uint8_t*)(B + (size_t)bcol * FCK);

    float acc[4][4][4];
    GEMM_MAINLOOP_B(Ar, Br, FCK * 2, (FCK * 2) / 128, MMA_FP16)

    const int rbase = brow + wr * 64 + (lane >> 2);
    const int cbase = bcol + wc * 32 + (lane & 3) * 2;
    #pragma unroll
    for (int mt = 0; mt < 4; ++mt) {
        #pragma unroll
        for (int nt = 0; nt < 4; ++nt) {
            float2 v0, v1;
            v0.x = fmaxf(acc[mt][nt][0], 0.f); v0.y = fmaxf(acc[mt][nt][1], 0.f);
            v1.x = fmaxf(acc[mt][nt][2], 0.f); v1.y = fmaxf(acc[mt][nt][3], 0.f);
            const int row = rbase + mt * 16;
            const int col = cbase + nt * 8;
            *(float2*)(C + (size_t)row * DIM + col)       = v0;
            *(float2*)(C + (size_t)(row + 8) * DIM + col) = v1;
        }
    }
}

// ---------------- ordering helpers (jax.lax.top_k: desc value, tie -> low idx) -
__device__ __forceinline__ bool pref(float v, int i, float v2, int i2)
{
    return (v > v2) || (v == v2 && i < i2);
}

__device__ __forceinline__ void ins3(float v, int i, float tv[3], int ti[3])
{
    if (!pref(v, i, tv[2], ti[2])) return;
    tv[2] = v; ti[2] = i;
    if (pref(tv[2], ti[2], tv[1], ti[1])) {
        float fv = tv[1]; int fi = ti[1];
        tv[1] = tv[2]; ti[1] = ti[2]; tv[2] = fv; ti[2] = fi;
    }
    if (pref(tv[1], ti[1], tv[0], ti[0])) {
        float fv = tv[0]; int fi = ti[0];
        tv[0] = tv[1]; ti[0] = ti[1]; tv[1] = fv; ti[1] = fi;
    }
}

// ---------------- 3a. top-8 per row: register-resident, u32 keys ---------------
__device__ __forceinline__ uint32_t mono2(uint32_t x)
{
    const uint32_t s = x & 0x80008000u;
    return x ^ (((s >> 15) * 0x7FFFu) | 0x80008000u);
}

__global__ void __launch_bounds__(256) top8_k(void)
{
    const int row  = blockIdx.x * 8 + (threadIdx.x >> 5);
    const int lane = threadIdx.x & 31;
    const uint4* d = (const uint4*)(g_disb + (size_t)row * NPTS);

    uint4 u[8];
    #pragma unroll
    for (int it = 0; it < 8; ++it) u[it] = d[it * 32 + lane];

    uint32_t mm2 = 0;
    #pragma unroll
    for (int it = 0; it < 8; ++it) {
        u[it].x = mono2(u[it].x); u[it].y = mono2(u[it].y);
        u[it].z = mono2(u[it].z); u[it].w = mono2(u[it].w);
        mm2 = __vmaxu2(mm2, u[it].x); mm2 = __vmaxu2(mm2, u[it].y);
        mm2 = __vmaxu2(mm2, u[it].z); mm2 = __vmaxu2(mm2, u[it].w);
    }
    const uint32_t lmax = max(mm2 >> 16, mm2 & 0xFFFFu);

    uint32_t live = lmax, T = 0;
    #pragma unroll
    for (int r = 0; r < 8; ++r) {
        uint32_t m = live;
        #pragma unroll
        for (int o = 16; o; o >>= 1) {
            uint32_t oth = __shfl_xor_sync(0xffffffffu, m, o);
            if (oth > m) m = oth;
        }
        if (live == m) live = 0;
        T = m;
    }
    const uint32_t Tkey = T << 16;

    uint32_t t[8];
    #pragma unroll
    for (int e = 0; e < 8; ++e) t[e] = Tkey;

    #pragma unroll
    for (int it = 0; it < 8; ++it) {
        const int base = (it * 32 + lane) * 8;
        const uint32_t w[4] = { u[it].x, u[it].y, u[it].z, u[it].w };
        #pragma unroll
        for (int h = 0; h < 4; ++h) {
            const uint32_t klo = (w[h] << 16)          | (0xFFFFu - (base + h * 2));
            const uint32_t khi = (w[h] & 0xFFFF0000u)  | (0xFFFFu - (base + h * 2 + 1));
            if (klo > t[7]) {
                t[7] = klo;
                #pragma unroll
                for (int e = 7; e > 0; --e) {
                    const uint32_t hi = max(t[e - 1], t[e]);
                    const uint32_t lo = min(t[e - 1], t[e]);
                    t[e - 1] = hi; t[e] = lo;
                }
            }
            if (khi > t[7]) {
                t[7] = khi;
                #pragma unroll
                for (int e = 7; e > 0; --e) {
                    const uint32_t hi = max(t[e - 1], t[e]);
                    const uint32_t lo = min(t[e - 1], t[e]);
                    t[e - 1] = hi; t[e] = lo;
                }
            }
        }
    }

    int out[8];
    #pragma unroll
    for (int r = 0; r < 8; ++r) {
        uint32_t m = t[0];
        #pragma unroll
        for (int o = 16; o; o >>= 1) {
            const uint32_t oth = __shfl_xor_sync(0xffffffffu, m, o);
            if (oth > m) m = oth;
        }
        if (t[0] == m) {
            t[0] = t[1]; t[1] = t[2]; t[2] = t[3]; t[3] = t[4];
            t[4] = t[5]; t[5] = t[6]; t[6] = t[7]; t[7] = 0u;
        }
        out[r] = (int)(0xFFFFu - (m & 0xFFFFu));
    }
    if (lane == 0) {
        #pragma unroll
        for (int e = 0; e < 8; ++e) g_idx8[(size_t)row * 8 + e] = out[e];
    }
}

// ---------------- 3b. exact fp32 rescore: cosine from raw feats + inv norms ---
__global__ void __launch_bounds__(256) rescore_k(const float* __restrict__ feats)
{
    const int gw   = blockIdx.x * 8 + (threadIdx.x >> 5);
    const int lane = threadIdx.x & 31;
    const int b    = gw >> 11;

    const float4* xrow = (const float4*)(feats + (size_t)gw * DIM);
    float4 x[4];
    #pragma unroll
    for (int q = 0; q < 4; ++q) x[q] = xrow[q * 32 + lane];
    const float inv_x = g_inorm[gw];

    float bv[3] = { -1e30f, -1e30f, -1e30f };
    int   bi[3] = { 0x7fffffff, 0x7fffffff, 0x7fffffff };

    #pragma unroll
    for (int c = 0; c < 8; ++c) {
        const int cand = g_idx8[(size_t)gw * 8 + c];
        const size_t gcand = (size_t)(b << 11) + cand;
        const float4* yr = (const float4*)(feats + gcand * DIM);
        float s = 0.0f;
        #pragma unroll
        for (int q = 0; q < 4; ++q) {
            const float4 y = yr[q * 32 + lane];
            s += x[q].x * y.x + x[q].y * y.y + x[q].z * y.z + x[q].w * y.w;
        }
        #pragma unroll
        for (int o = 16; o; o >>= 1) s += __shfl_xor_sync(0xffffffffu, s, o);
        s = s * inv_x * g_inorm[gcand];
        ins3(s, cand, bv, bi);
    }
    if (lane == 0) {
        g_idx[gw * 3 + 0] = bi[0];
        g_idx[gw * 3 + 1] = bi[1];
        g_idx[gw * 3 + 2] = bi[2];
    }
}

// ---------------- 4. gather + conv-mapping + softmax + pool + fcA split -------
__global__ void __launch_bounds__(256) conv_pool2_k(
    const float* __restrict__ feats,
    const float* __restrict__ convw,
    const float* __restrict__ convb)
{
    __shared__ float wsm[9 * DIM];
    const int tid = threadIdx.x, lane = tid & 31, wid = tid >> 5;

    for (int i = tid; i < 9 * DIM / 4; i += 256)
        ((float4*)wsm)[i] = ((const float4*)convw)[i];
    __syncthreads();

    const int node = blockIdx.x * 8 + wid;
    const int b = node >> 11;
    const float* fb = feats + (size_t)b * NPTS * DIM;

    float4 kr[3][4];
    #pragma unroll
    for (int g = 0; g < 3; ++g) {
        const int id = g_idx[(size_t)node * 3 + g];
        const float4* yp = (const float4*)(fb + (size_t)id * DIM);
        #pragma unroll
        for (int q = 0; q < 4; ++q) kr[g][q] = yp[q * 32 + lane];
    }

    float p[9];
    #pragma unroll
    for (int q9 = 0; q9 < 9; ++q9) p[q9] = 0.0f;
    #pragma unroll
    for (int q = 0; q < 4; ++q) {
        const int col4 = q * 32 + lane;
        #pragma unroll
        for (int g = 0; g < 3; ++g) {
            const float4 kv = kr[g][q];
            #pragma unroll
            for (int j = 0; j < 3; ++j) {
                const float4 wv = ((const float4*)wsm)[(g * 3 + j) * 128 + col4];
                p[g * 3 + j] += kv.x * wv.x + kv.y * wv.y + kv.z * wv.z + kv.w * wv.w;
            }
        }
    }
    #pragma unroll
    for (int q9 = 0; q9 < 9; ++q9)
        #pragma unroll
        for (int o = 16; o; o >>= 1) p[q9] += __shfl_xor_sync(0xffffffffu, p[q9], o);

    float w0 = 0.f, w1 = 0.f, w2 = 0.f;
    #pragma unroll
    for (int g = 0; g < 3; ++g) {
        const float m0 = p[g * 3 + 0] + __ldg(convb + g * 3 + 0);
        const float m1 = p[g * 3 + 1] + __ldg(convb + g * 3 + 1);
        const float m2 = p[g * 3 + 2] + __ldg(convb + g * 3 + 2);
        const float mx = fmaxf(m0, fmaxf(m1, m2));
        const float e0 = expf(m0 - mx), e1 = expf(m1 - mx), e2 = expf(m2 - mx);
        const float inv = 1.0f / (e0 + e1 + e2);
        w0 += e0 * inv; w1 += e1 * inv; w2 += e2 * inv;
    }
    const float third = 1.0f / 3.0f;
    const float c0 = w0 * third, c1 = w1 * third, c2 = w2 * third;

    __half* ap = g_fcA + (size_t)node * FCK;
    #pragma unroll
    for (int q = 0; q < 4; ++q) {
        float4 o;
        o.x = c0 * kr[0][q].x + c1 * kr[1][q].x + c2 * kr[2][q].x;
        o.y = c0 * kr[0][q].y + c1 * kr[1][q].y + c2 * kr[2][q].y;
        o.z = c0 * kr[0][q].z + c1 * kr[1][q].z + c2 * kr[2][q].z;
        o.w = c0 * kr[0][q].w + c1 * kr[1][q].w + c2 * kr[2][q].w;
        __half2 h01, h23, l01, l23;
        h01.x = __float2half_rn(o.x); h01.y = __float2half_rn(o.y);
        h23.x = __float2half_rn(o.z); h23.y = __float2half_rn(o.w);
        l01.x = __float2half_rn(o.x - __half2float(h01.x));
        l01.y = __float2half_rn(o.y - __half2float(h01.y));
        l23.x = __float2half_rn(o.z - __half2float(h23.x));
        l23.y = __float2half_rn(o.w - __half2float(h23.y));
        const int c = (q * 32 + lane) * 4;
        __half2* dst = (__half2*)ap;
        dst[c / 2]          = h01; dst[c / 2 + 1]          = h23;  // [0,512): hi
        dst[(c + 512) / 2]  = l01; dst[(c + 512) / 2 + 1]  = l23;  // [512,1024): lo
    }
}

// ---------------- split fc weights: fp16 [hi, hi] ------------------------------
__global__ void __launch_bounds__(128) splitB_k(const float* __restrict__ fcw)
{
    const size_t row = blockIdx.x;
    const int c = threadIdx.x * 4;
    const float4 v = ((const float4*)(fcw + row * DIM))[threadIdx.x];
    __half2 h01, h23;
    h01.x = __float2half_rn(v.x); h01.y = __float2half_rn(v.y);
    h23.x = __float2half_rn(v.z); h23.y = __float2half_rn(v.w);
    __half2* dst = (__half2*)(g_fcB + row * FCK);
    dst[c / 2]          = h01; dst[c / 2 + 1]          = h23;  // hi
    dst[(c + 512) / 2]  = h01; dst[(c + 512) / 2 + 1]  = h23;  // hi (again)
}

// ---------------- launch -------------------------------------------------------
extern "C" void kernel_launch(void* const* d_in, const int* in_sizes, int n_in,
                              void* d_out, int out_size)
{
    const float* feats = (const float*)d_in[0];
    const float* convw = (const float*)d_in[1];
    const float* convb = (const float*)d_in[2];
    const float* fcw   = (const float*)d_in[3];
    float* out = (float*)d_out;

    void *xq_p, *dis_p, *fcA_p, *fcB_p;
    cudaGetSymbolAddress(&xq_p, g_xq);
    cudaGetSymbolAddress(&dis_p, g_disb);
    cudaGetSymbolAddress(&fcA_p, g_fcA);
    cudaGetSymbolAddress(&fcB_p, g_fcB);

    const int smem_bytes = 100 * 1024;   // 3 stages x 32KB + alignment
    cudaFuncSetAttribute(gemm_sym_k,
                         cudaFuncAttributeMaxDynamicSharedMemorySize, smem_bytes);
    cudaFuncSetAttribute(gemm_fc_k,
                         cudaFuncAttributeMaxDynamicSharedMemorySize, smem_bytes);

    // 1. normalize rows (e4m3 copy + inverse norms)
    normalize_k<<<NROWS, 128>>>(feats);

    // split fc weights early (independent)
    splitB_k<<<DIM, 128>>>(fcw);

    // 2. cosine similarity: symmetric fp8 GEMM, bf16 score store + mirror
    {
        dim3 grid(NTRI, 1, BATCH);
        gemm_sym_k<<<grid, 256, smem_bytes>>>(
            (const uint8_t*)xq_p, (__nv_bfloat16*)dis_p);
    }

    // 3. top-8 candidates (register-resident u32 keys), exact rescore -> top-3
    top8_k<<<NROWS / 8, 256>>>();
    rescore_k<<<NROWS / 8, 256>>>(feats);

    // 4. gather + conv mapping + softmax + pool, fused fp16 hi/lo split
    conv_pool2_k<<<NROWS / 8, 256>>>(feats, convw, convb);

    // 5. fc + relu: fp16 2-term GEMM, K=1024
    {
        dim3 grid(DIM / 128, NROWS / 128, 1);
        gemm_fc_k<<<grid, 256, smem_bytes>>>(
            (const __half*)fcA_p, (const __half*)fcB_p, out);
    }
}

// round 14
// speedup vs baseline: 1.1817x; 1.1817x over previous
#include <cuda_runtime.h>
#include <cuda_bf16.h>
#include <cuda_fp16.h>
#include <math.h>
#include <stdint.h>

// Problem constants (fixed by the dataset)
#define BATCH 8
#define NPTS  2048
#define DIM   512
#define KN    3
#define NROWS (BATCH * NPTS)   // 16384
#define FCK   512              // plain fp16 fc GEMM
#define NTILE 16               // 2048 / 128
#define NTRI  136              // NTILE*(NTILE+1)/2 upper-triangle tiles

// ---------------- scratch (static device memory; no allocs allowed) ----------
__device__ __nv_bfloat16 g_xnb[(size_t)NROWS * DIM];            // 16 MB bf16 normalized
__device__ float         g_inorm[(size_t)NROWS];                // 64 KB inverse norms
__device__ __nv_bfloat16 g_disb[(size_t)BATCH * NPTS * NPTS];   // 67 MB bf16 scores
__device__ int           g_idx8[(size_t)NROWS * 8];
__device__ int           g_idx [(size_t)NROWS * KN];
__device__ __half        g_fcA[(size_t)NROWS * FCK];            // 16 MB fp16 pooled
__device__ __half        g_fcB[(size_t)DIM * FCK];              // 0.5 MB fp16 weights

// ============================ PTX helpers ======================================
__device__ __forceinline__ uint32_t smem_u32(const void* p) {
    uint32_t a;
    asm("{ .reg .u64 t; cvta.to.shared.u64 t, %1; cvt.u32.u64 %0, t; }"
        : "=r"(a) : "l"(p));
    return a;
}

#define CP_ASYNC16(saddr, gptr) \
    asm volatile("cp.async.cg.shared.global [%0], [%1], 16;" \
                 :: "r"(saddr), "l"(gptr) : "memory")
#define CP_COMMIT()  asm volatile("cp.async.commit_group;" ::: "memory")
#define CP_WAIT1()   asm volatile("cp.async.wait_group 1;" ::: "memory")
#define CP_WAIT0()   asm volatile("cp.async.wait_group 0;" ::: "memory")

#define LDMATRIX_X4(r, addr) \
    asm volatile("ldmatrix.sync.aligned.m8n8.x4.shared.b16 {%0,%1,%2,%3}, [%4];" \
        : "=r"((r)[0]), "=r"((r)[1]), "=r"((r)[2]), "=r"((r)[3]) : "r"(addr))

#define MMA_BF16(c, a, b0, b1) \
    asm volatile("mma.sync.aligned.m16n8k16.row.col.f32.bf16.bf16.f32 " \
        "{%0,%1,%2,%3}, {%4,%5,%6,%7}, {%8,%9}, {%0,%1,%2,%3};" \
        : "+f"((c)[0]), "+f"((c)[1]), "+f"((c)[2]), "+f"((c)[3]) \
        : "r"((a)[0]), "r"((a)[1]), "r"((a)[2]), "r"((a)[3]), "r"(b0), "r"(b1))

#define MMA_FP16(c, a, b0, b1) \
    asm volatile("mma.sync.aligned.m16n8k16.row.col.f32.f16.f16.f32 " \
        "{%0,%1,%2,%3}, {%4,%5,%6,%7}, {%8,%9}, {%0,%1,%2,%3};" \
        : "+f"((c)[0]), "+f"((c)[1]), "+f"((c)[2]), "+f"((c)[3]) \
        : "r"((a)[0]), "r"((a)[1]), "r"((a)[2]), "r"((a)[3]), "r"(b0), "r"(b1))

// Shared GEMM mainloop: 3-stage cp.async pipeline, ONE __syncthreads per chunk.
// MMAOP selects the 16-bit mma flavor (bf16 or fp16); element size is 2B both.
#define GEMM_MAINLOOP(Ar, Br, K, MMAOP)                                        \
    const int seg = tid & 7;                                                   \
    const int r0  = tid >> 3;                                                  \
    auto load_chunk = [&](int c, int stage) {                                  \
        const uint32_t dA = sbase + stage * 32768;                             \
        const uint32_t dB = dA + 16384;                                        \
        const size_t koff = (size_t)c * 64 + seg * 8;                          \
        _Pragma("unroll")                                                      \
        for (int it = 0; it < 4; ++it) {                                       \
            const int r = r0 + it * 32;                                        \
            uint32_t off = r * 128 + seg * 16;                                 \
            off ^= (off >> 3) & 0x70;                                          \
            CP_ASYNC16(dA + off, (Ar) + (size_t)r * (K) + koff);               \
            CP_ASYNC16(dB + off, (Br) + (size_t)r * (K) + koff);               \
        }                                                                      \
    };                                                                         \
    _Pragma("unroll")                                                          \
    for (int mt = 0; mt < 4; ++mt)                                             \
        _Pragma("unroll")                                                      \
        for (int nt = 0; nt < 4; ++nt)                                         \
            _Pragma("unroll")                                                  \
            for (int q = 0; q < 4; ++q) acc[mt][nt][q] = 0.0f;                 \
    const int nk = (K) >> 6;                                                   \
    load_chunk(0, 0);                                                          \
    CP_COMMIT();                                                               \
    load_chunk(1, 1);                                                          \
    CP_COMMIT();                                                               \
    const int mi = lane >> 3;                                                  \
    const int l7 = lane & 7;                                                   \
    _Pragma("unroll 1")                                                        \
    for (int c = 0; c < nk; ++c) {                                             \
        const int st = c % 3;                                                  \
        if (c + 1 < nk) { CP_WAIT1(); } else { CP_WAIT0(); }                   \
        __syncthreads();                                                       \
        if (c + 2 < nk) { load_chunk(c + 2, (c + 2) % 3); CP_COMMIT(); }       \
        const uint32_t tA = sbase + st * 32768;                                \
        const uint32_t tB = tA + 16384;                                        \
        _Pragma("unroll")                                                      \
        for (int ks = 0; ks < 4; ++ks) {                                       \
            uint32_t a[4][4], b[2][4];                                         \
            _Pragma("unroll")                                                  \
            for (int mt = 0; mt < 4; ++mt) {                                   \
                const int row = wr * 64 + mt * 16 + l7 + ((mi & 1) << 3);      \
                const int sg  = ks * 2 + (mi >> 1);                            \
                uint32_t off = row * 128 + sg * 16;                            \
                off ^= (off >> 3) & 0x70;                                      \
                LDMATRIX_X4(a[mt], tA + off);                                  \
            }                                                                  \
            _Pragma("unroll")                                                  \
            for (int np = 0; np < 2; ++np) {                                   \
                const int n  = wc * 32 + np * 16 + l7 + ((mi >> 1) << 3);      \
                const int sg = ks * 2 + (mi & 1);                              \
                uint32_t off = n * 128 + sg * 16;                              \
                off ^= (off >> 3) & 0x70;                                      \
                LDMATRIX_X4(b[np], tB + off);                                  \
            }                                                                  \
            _Pragma("unroll")                                                  \
            for (int mt = 0; mt < 4; ++mt)                                     \
                _Pragma("unroll")                                              \
                for (int nt = 0; nt < 4; ++nt)                                 \
                    MMAOP(acc[mt][nt], a[mt],                                  \
                          b[nt >> 1][(nt & 1) * 2], b[nt >> 1][(nt & 1) * 2 + 1]); \
        }                                                                      \
    }

// ---------------- 1. row L2-normalize: bf16 copy + inverse norm ----------------
__global__ void __launch_bounds__(128) normalize_k(const float* __restrict__ feats)
{
    const size_t row = blockIdx.x;
    const float4 v = ((const float4*)(feats + row * DIM))[threadIdx.x];
    float ss = v.x * v.x + v.y * v.y + v.z * v.z + v.w * v.w;
    #pragma unroll
    for (int o = 16; o; o >>= 1) ss += __shfl_xor_sync(0xffffffffu, ss, o);
    __shared__ float s[4];
    if ((threadIdx.x & 31) == 0) s[threadIdx.x >> 5] = ss;
    __syncthreads();
    const float tot = s[0] + s[1] + s[2] + s[3];
    const float inv = 1.0f / fmaxf(sqrtf(tot), 1e-12f);
    __nv_bfloat162 b0, b1;
    b0.x = __float2bfloat16(v.x * inv); b0.y = __float2bfloat16(v.y * inv);
    b1.x = __float2bfloat16(v.z * inv); b1.y = __float2bfloat16(v.w * inv);
    ((__nv_bfloat162*)(g_xnb + row * DIM))[threadIdx.x * 2]     = b0;
    ((__nv_bfloat162*)(g_xnb + row * DIM))[threadIdx.x * 2 + 1] = b1;
    if (threadIdx.x == 0) g_inorm[row] = inv;
}

// ---------------- 2. symmetric similarity GEMM (upper-triangle tiles) ---------
__global__ void __launch_bounds__(256, 2) gemm_sym_k(
    const __nv_bfloat16* __restrict__ xnb, __nv_bfloat16* __restrict__ dis)
{
    extern __shared__ char smem_raw[];
    char* tiles = (char*)(((uintptr_t)smem_raw + 1023) & ~(uintptr_t)1023);
    const uint32_t sbase = smem_u32(tiles);

    int t = blockIdx.x, ti = 0;
    while (t >= NTILE - ti) { t -= NTILE - ti; ++ti; }
    const int tj = ti + t;
    const int brow = ti * 128, bcol = tj * 128;

    const __nv_bfloat16* base = xnb + (size_t)blockIdx.z * NPTS * DIM;
    __nv_bfloat16* C = dis + (size_t)blockIdx.z * NPTS * NPTS;

    const int tid  = threadIdx.x;
    const int lane = tid & 31, wid = tid >> 5;
    const int wr = wid >> 2, wc = wid & 3;

    const __nv_bfloat16* Ar = base + (size_t)brow * DIM;
    const __nv_bfloat16* Br = base + (size_t)bcol * DIM;

    float acc[4][4][4];
    GEMM_MAINLOOP(Ar, Br, DIM, MMA_BF16)

    // direct bf16 store (col even -> 4B-aligned bf162)
    const int rbase = wr * 64 + (lane >> 2);
    const int cbase = wc * 32 + (lane & 3) * 2;
    #pragma unroll
    for (int mt = 0; mt < 4; ++mt) {
        #pragma unroll
        for (int nt = 0; nt < 4; ++nt) {
            const int row = rbase + mt * 16;
            const int col = cbase + nt * 8;
            __nv_bfloat162 b0, b1;
            b0.x = __float2bfloat16(acc[mt][nt][0]);
            b0.y = __float2bfloat16(acc[mt][nt][1]);
            b1.x = __float2bfloat16(acc[mt][nt][2]);
            b1.y = __float2bfloat16(acc[mt][nt][3]);
            *(__nv_bfloat162*)(C + (size_t)(brow + row) * NPTS + bcol + col)     = b0;
            *(__nv_bfloat162*)(C + (size_t)(brow + row + 8) * NPTS + bcol + col) = b1;
        }
    }

    if (ti != tj) {
        __syncthreads();   // last chunk's ldmatrix reads must finish before reuse
        float* Cs = (float*)tiles;
        #pragma unroll
        for (int mt = 0; mt < 4; ++mt) {
            #pragma unroll
            for (int nt = 0; nt < 4; ++nt) {
                const int row = rbase + mt * 16;
                const int col = cbase + nt * 8;
                Cs[row * 129 + col]           = acc[mt][nt][0];
                Cs[row * 129 + col + 1]       = acc[mt][nt][1];
                Cs[(row + 8) * 129 + col]     = acc[mt][nt][2];
                Cs[(row + 8) * 129 + col + 1] = acc[mt][nt][3];
            }
        }
        __syncthreads();
        #pragma unroll 8
        for (int it2 = 0; it2 < 64; ++it2) {
            const int linear = it2 * 256 + tid;
            const int r2 = linear >> 7;
            const int c2 = linear & 127;
            C[(size_t)(bcol + r2) * NPTS + brow + c2] =
                __float2bfloat16(Cs[c2 * 129 + r2]);
        }
    }
}

// ---------------- 2b. fc GEMM: plain fp16, K=512, relu store -------------------
__global__ void __launch_bounds__(256, 2) gemm_fc_k(
    const __half* __restrict__ A, const __half* __restrict__ B,
    float* __restrict__ C)
{
    extern __shared__ char smem_raw[];
    char* tiles = (char*)(((uintptr_t)smem_raw + 1023) & ~(uintptr_t)1023);
    const uint32_t sbase = smem_u32(tiles);

    const int tid  = threadIdx.x;
    const int lane = tid & 31, wid = tid >> 5;
    const int wr = wid >> 2, wc = wid & 3;
    const int brow = blockIdx.y * 128, bcol = blockIdx.x * 128;

    const __half* Ar = A + (size_t)brow * FCK;
    const __half* Br = B + (size_t)bcol * FCK;

    float acc[4][4][4];
    GEMM_MAINLOOP(Ar, Br, FCK, MMA_FP16)

    const int rbase = brow + wr * 64 + (lane >> 2);
    const int cbase = bcol + wc * 32 + (lane & 3) * 2;
    #pragma unroll
    for (int mt = 0; mt < 4; ++mt) {
        #pragma unroll
        for (int nt = 0; nt < 4; ++nt) {
            float2 v0, v1;
            v0.x = fmaxf(acc[mt][nt][0], 0.f); v0.y = fmaxf(acc[mt][nt][1], 0.f);
            v1.x = fmaxf(acc[mt][nt][2], 0.f); v1.y = fmaxf(acc[mt][nt][3], 0.f);
            const int row = rbase + mt * 16;
            const int col = cbase + nt * 8;
            *(float2*)(C + (size_t)row * DIM + col)       = v0;
            *(float2*)(C + (size_t)(row + 8) * DIM + col) = v1;
        }
    }
}

// ---------------- ordering helpers (jax.lax.top_k: desc value, tie -> low idx) -
__device__ __forceinline__ bool pref(float v, int i, float v2, int i2)
{
    return (v > v2) || (v == v2 && i < i2);
}

__device__ __forceinline__ void ins3(float v, int i, float tv[3], int ti[3])
{
    if (!pref(v, i, tv[2], ti[2])) return;
    tv[2] = v; ti[2] = i;
    if (pref(tv[2], ti[2], tv[1], ti[1])) {
        float fv = tv[1]; int fi = ti[1];
        tv[1] = tv[2]; ti[1] = ti[2]; tv[2] = fv; ti[2] = fi;
    }
    if (pref(tv[1], ti[1], tv[0], ti[0])) {
        float fv = tv[0]; int fi = ti[0];
        tv[0] = tv[1]; ti[0] = ti[1]; tv[1] = fv; ti[1] = fi;
    }
}

// ---------------- 3a. top-8 per row: register-resident, u32 keys ---------------
__device__ __forceinline__ uint32_t mono2(uint32_t x)
{
    const uint32_t s = x & 0x80008000u;
    return x ^ (((s >> 15) * 0x7FFFu) | 0x80008000u);
}

__global__ void __launch_bounds__(256) top8_k(void)
{
    const int row  = blockIdx.x * 8 + (threadIdx.x >> 5);
    const int lane = threadIdx.x & 31;
    const uint4* d = (const uint4*)(g_disb + (size_t)row * NPTS);

    uint4 u[8];
    #pragma unroll
    for (int it = 0; it < 8; ++it) u[it] = d[it * 32 + lane];

    uint32_t mm2 = 0;
    #pragma unroll
    for (int it = 0; it < 8; ++it) {
        u[it].x = mono2(u[it].x); u[it].y = mono2(u[it].y);
        u[it].z = mono2(u[it].z); u[it].w = mono2(u[it].w);
        mm2 = __vmaxu2(mm2, u[it].x); mm2 = __vmaxu2(mm2, u[it].y);
        mm2 = __vmaxu2(mm2, u[it].z); mm2 = __vmaxu2(mm2, u[it].w);
    }
    const uint32_t lmax = max(mm2 >> 16, mm2 & 0xFFFFu);

    uint32_t live = lmax, T = 0;
    #pragma unroll
    for (int r = 0; r < 8; ++r) {
        uint32_t m = live;
        #pragma unroll
        for (int o = 16; o; o >>= 1) {
            uint32_t oth = __shfl_xor_sync(0xffffffffu, m, o);
            if (oth > m) m = oth;
        }
        if (live == m) live = 0;
        T = m;
    }
    const uint32_t Tkey = T << 16;

    uint32_t t[8];
    #pragma unroll
    for (int e = 0; e < 8; ++e) t[e] = Tkey;

    #pragma unroll
    for (int it = 0; it < 8; ++it) {
        const int base = (it * 32 + lane) * 8;
        const uint32_t w[4] = { u[it].x, u[it].y, u[it].z, u[it].w };
        #pragma unroll
        for (int h = 0; h < 4; ++h) {
            const uint32_t klo = (w[h] << 16)          | (0xFFFFu - (base + h * 2));
            const uint32_t khi = (w[h] & 0xFFFF0000u)  | (0xFFFFu - (base + h * 2 + 1));
            if (klo > t[7]) {
                t[7] = klo;
                #pragma unroll
                for (int e = 7; e > 0; --e) {
                    const uint32_t hi = max(t[e - 1], t[e]);
                    const uint32_t lo = min(t[e - 1], t[e]);
                    t[e - 1] = hi; t[e] = lo;
                }
            }
            if (khi > t[7]) {
                t[7] = khi;
                #pragma unroll
                for (int e = 7; e > 0; --e) {
                    const uint32_t hi = max(t[e - 1], t[e]);
                    const uint32_t lo = min(t[e - 1], t[e]);
                    t[e - 1] = hi; t[e] = lo;
                }
            }
        }
    }

    int out[8];
    #pragma unroll
    for (int r = 0; r < 8; ++r) {
        uint32_t m = t[0];
        #pragma unroll
        for (int o = 16; o; o >>= 1) {
            const uint32_t oth = __shfl_xor_sync(0xffffffffu, m, o);
            if (oth > m) m = oth;
        }
        if (t[0] == m) {
            t[0] = t[1]; t[1] = t[2]; t[2] = t[3]; t[3] = t[4];
            t[4] = t[5]; t[5] = t[6]; t[6] = t[7]; t[7] = 0u;
        }
        out[r] = (int)(0xFFFFu - (m & 0xFFFFu));
    }
    if (lane == 0) {
        #pragma unroll
        for (int e = 0; e < 8; ++e) g_idx8[(size_t)row * 8 + e] = out[e];
    }
}

// ---------------- 3b. exact fp32 rescore: cosine from raw feats + inv norms ---
__global__ void __launch_bounds__(256) rescore_k(const float* __restrict__ feats)
{
    const int gw   = blockIdx.x * 8 + (threadIdx.x >> 5);
    const int lane = threadIdx.x & 31;
    const int b    = gw >> 11;

    const float4* xrow = (const float4*)(feats + (size_t)gw * DIM);
    float4 x[4];
    #pragma unroll
    for (int q = 0; q < 4; ++q) x[q] = xrow[q * 32 + lane];
    const float inv_x = g_inorm[gw];

    float bv[3] = { -1e30f, -1e30f, -1e30f };
    int   bi[3] = { 0x7fffffff, 0x7fffffff, 0x7fffffff };

    #pragma unroll
    for (int c = 0; c < 8; ++c) {
        const int cand = g_idx8[(size_t)gw * 8 + c];
        const size_t gcand = (size_t)(b << 11) + cand;
        const float4* yr = (const float4*)(feats + gcand * DIM);
        float s = 0.0f;
        #pragma unroll
        for (int q = 0; q < 4; ++q) {
            const float4 y = yr[q * 32 + lane];
            s += x[q].x * y.x + x[q].y * y.y + x[q].z * y.z + x[q].w * y.w;
        }
        #pragma unroll
        for (int o = 16; o; o >>= 1) s += __shfl_xor_sync(0xffffffffu, s, o);
        s = s * inv_x * g_inorm[gcand];
        ins3(s, cand, bv, bi);
    }
    if (lane == 0) {
        g_idx[gw * 3 + 0] = bi[0];
        g_idx[gw * 3 + 1] = bi[1];
        g_idx[gw * 3 + 2] = bi[2];
    }
}

// ---------------- 4. gather + conv-mapping + softmax + pool, fp16 store -------
__global__ void __launch_bounds__(256) conv_pool2_k(
    const float* __restrict__ feats,
    const float* __restrict__ convw,
    const float* __restrict__ convb)
{
    __shared__ float wsm[9 * DIM];
    const int tid = threadIdx.x, lane = tid & 31, wid = tid >> 5;

    for (int i = tid; i < 9 * DIM / 4; i += 256)
        ((float4*)wsm)[i] = ((const float4*)convw)[i];
    __syncthreads();

    const int node = blockIdx.x * 8 + wid;
    const int b = node >> 11;
    const float* fb = feats + (size_t)b * NPTS * DIM;

    float4 kr[3][4];
    #pragma unroll
    for (int g = 0; g < 3; ++g) {
        const int id = g_idx[(size_t)node * 3 + g];
        const float4* yp = (const float4*)(fb + (size_t)id * DIM);
        #pragma unroll
        for (int q = 0; q < 4; ++q) kr[g][q] = yp[q * 32 + lane];
    }

    float p[9];
    #pragma unroll
    for (int q9 = 0; q9 < 9; ++q9) p[q9] = 0.0f;
    #pragma unroll
    for (int q = 0; q < 4; ++q) {
        const int col4 = q * 32 + lane;
        #pragma unroll
        for (int g = 0; g < 3; ++g) {
            const float4 kv = kr[g][q];
            #pragma unroll
            for (int j = 0; j < 3; ++j) {
                const float4 wv = ((const float4*)wsm)[(g * 3 + j) * 128 + col4];
                p[g * 3 + j] += kv.x * wv.x + kv.y * wv.y + kv.z * wv.z + kv.w * wv.w;
            }
        }
    }
    #pragma unroll
    for (int q9 = 0; q9 < 9; ++q9)
        #pragma unroll
        for (int o = 16; o; o >>= 1) p[q9] += __shfl_xor_sync(0xffffffffu, p[q9], o);

    float w0 = 0.f, w1 = 0.f, w2 = 0.f;
    #pragma unroll
    for (int g = 0; g < 3; ++g) {
        const float m0 = p[g * 3 + 0] + __ldg(convb + g * 3 + 0);
        const float m1 = p[g * 3 + 1] + __ldg(convb + g * 3 + 1);
        const float m2 = p[g * 3 + 2] + __ldg(convb + g * 3 + 2);
        const float mx = fmaxf(m0, fmaxf(m1, m2));
        const float e0 = expf(m0 - mx), e1 = expf(m1 - mx), e2 = expf(m2 - mx);
        const float inv = 1.0f / (e0 + e1 + e2);
        w0 += e0 * inv; w1 += e1 * inv; w2 += e2 * inv;
    }
    const float third = 1.0f / 3.0f;
    const float c0 = w0 * third, c1 = w1 * third, c2 = w2 * third;

    __half2* dst = (__half2*)(g_fcA + (size_t)node * FCK);
    #pragma unroll
    for (int q = 0; q < 4; ++q) {
        float4 o;
        o.x = c0 * kr[0][q].x + c1 * kr[1][q].x + c2 * kr[2][q].x;
        o.y = c0 * kr[0][q].y + c1 * kr[1][q].y + c2 * kr[2][q].y;
        o.z = c0 * kr[0][q].z + c1 * kr[1][q].z + c2 * kr[2][q].z;
        o.w = c0 * kr[0][q].w + c1 * kr[1][q].w + c2 * kr[2][q].w;
        __half2 h01, h23;
        h01.x = __float2half_rn(o.x); h01.y = __float2half_rn(o.y);
        h23.x = __float2half_rn(o.z); h23.y = __float2half_rn(o.w);
        const int c = (q * 32 + lane) * 4;
        dst[c / 2]     = h01;
        dst[c / 2 + 1] = h23;
    }
}

// ---------------- fc weights -> fp16 -------------------------------------------
__global__ void __launch_bounds__(128) splitB_k(const float* __restrict__ fcw)
{
    const size_t row = blockIdx.x;
    const int c = threadIdx.x * 4;
    const float4 v = ((const float4*)(fcw + row * DIM))[threadIdx.x];
    __half2 h01, h23;
    h01.x = __float2half_rn(v.x); h01.y = __float2half_rn(v.y);
    h23.x = __float2half_rn(v.z); h23.y = __float2half_rn(v.w);
    __half2* dst = (__half2*)(g_fcB + row * FCK);
    dst[c / 2]     = h01;
    dst[c / 2 + 1] = h23;
}

// ---------------- launch -------------------------------------------------------
extern "C" void kernel_launch(void* const* d_in, const int* in_sizes, int n_in,
                              void* d_out, int out_size)
{
    const float* feats = (const float*)d_in[0];
    const float* convw = (const float*)d_in[1];
    const float* convb = (const float*)d_in[2];
    const float* fcw   = (const float*)d_in[3];
    float* out = (float*)d_out;

    void *xnb_p, *dis_p, *fcA_p, *fcB_p;
    cudaGetSymbolAddress(&xnb_p, g_xnb);
    cudaGetSymbolAddress(&dis_p, g_disb);
    cudaGetSymbolAddress(&fcA_p, g_fcA);
    cudaGetSymbolAddress(&fcB_p, g_fcB);

    const int smem_bytes = 100 * 1024;   // 3 stages x 32KB + alignment
    cudaFuncSetAttribute(gemm_sym_k,
                         cudaFuncAttributeMaxDynamicSharedMemorySize, smem_bytes);
    cudaFuncSetAttribute(gemm_fc_k,
                         cudaFuncAttributeMaxDynamicSharedMemorySize, smem_bytes);

    // 1. normalize rows (bf16 copy + inverse norms)
    normalize_k<<<NROWS, 128>>>(feats);

    // fc weights -> fp16 (independent)
    splitB_k<<<DIM, 128>>>(fcw);

    // 2. cosine similarity: symmetric bf16 GEMM, bf16 score store + mirror
    {
        dim3 grid(NTRI, 1, BATCH);
        gemm_sym_k<<<grid, 256, smem_bytes>>>(
            (const __nv_bfloat16*)xnb_p, (__nv_bfloat16*)dis_p);
    }

    // 3. top-8 candidates (register-resident u32 keys), exact rescore -> top-3
    top8_k<<<NROWS / 8, 256>>>();
    rescore_k<<<NROWS / 8, 256>>>(feats);

    // 4. gather + conv mapping + softmax + pool, fp16 store
    conv_pool2_k<<<NROWS / 8, 256>>>(feats, convw, convb);

    // 5. fc + relu: plain fp16 GEMM, K=512
    {
        dim3 grid(DIM / 128, NROWS / 128, 1);
        gemm_fc_k<<<grid, 256, smem_bytes>>>(
            (const __half*)fcA_p, (const __half*)fcB_p, out);
    }
}